// round 13
// baseline (speedup 1.0000x reference)
#include <cuda_runtime.h>
#include <cuda_bf16.h>
#include <cstdint>

#define BB 4
#define SS 2048
#define HH 1024

typedef __nv_bfloat16  bf16;
typedef __nv_bfloat162 bf162;

// ---------------- scratch (static device globals; no allocation) ----------------
__device__ __align__(256) bf16 g_xhi[(size_t)BB*SS*HH], g_xlo[(size_t)BB*SS*HH];
__device__ __align__(256) bf16 g_whi[(size_t)3*HH*HH],  g_wlo[(size_t)3*HH*HH];
__device__ __align__(256) bf16 g_qhi[(size_t)BB*SS*HH], g_qlo[(size_t)BB*SS*HH];
__device__ __align__(256) bf16 g_khi[(size_t)BB*SS*HH], g_klo[(size_t)BB*SS*HH];
__device__ __align__(256) bf16 g_vthi[(size_t)BB*HH*SS],g_vtlo[(size_t)BB*HH*SS];
__device__ __align__(256) float g_s[(size_t)BB*SS*SS];
__device__ __align__(256) bf16 g_phi[(size_t)BB*SS*SS], g_plo[(size_t)BB*SS*SS];

// ---------------- low-level helpers ----------------
static __device__ __forceinline__ void mma_bf16(float* d, const uint32_t* a, const uint32_t* b) {
    asm volatile(
        "mma.sync.aligned.m16n8k16.row.col.f32.bf16.bf16.f32 "
        "{%0,%1,%2,%3}, {%4,%5,%6,%7}, {%8,%9}, {%0,%1,%2,%3};\n"
        : "+f"(d[0]), "+f"(d[1]), "+f"(d[2]), "+f"(d[3])
        : "r"(a[0]), "r"(a[1]), "r"(a[2]), "r"(a[3]), "r"(b[0]), "r"(b[1]));
}

static __device__ __forceinline__ uint32_t smem_u32(const void* p) {
    return (uint32_t)__cvta_generic_to_shared(p);
}
static __device__ __forceinline__ void cp16(uint32_t dst, const void* src) {
    asm volatile("cp.async.cg.shared.global [%0], [%1], 16;\n" :: "r"(dst), "l"(src));
}
static __device__ __forceinline__ void cp_commit() { asm volatile("cp.async.commit_group;\n"); }
template <int N>
static __device__ __forceinline__ void cp_wait() {
    asm volatile("cp.async.wait_group %0;\n" :: "n"(N));
}
static __device__ __forceinline__ void ldm_x4(uint32_t* r, uint32_t addr) {
    asm volatile("ldmatrix.sync.aligned.m8n8.x4.shared.b16 {%0,%1,%2,%3}, [%4];\n"
        : "=r"(r[0]), "=r"(r[1]), "=r"(r[2]), "=r"(r[3]) : "r"(addr));
}
static __device__ __forceinline__ void ldm_x2(uint32_t* r, uint32_t addr) {
    asm volatile("ldmatrix.sync.aligned.m8n8.x2.shared.b16 {%0,%1}, [%2];\n"
        : "=r"(r[0]), "=r"(r[1]) : "r"(addr));
}

static __device__ __forceinline__ void split2(float x, float y, bf162& h2, bf162& l2) {
    bf16 hx = __float2bfloat16_rn(x);
    bf16 hy = __float2bfloat16_rn(y);
    h2 = __halves2bfloat162(hx, hy);
    l2 = __halves2bfloat162(__float2bfloat16_rn(x - __bfloat162float(hx)),
                            __float2bfloat16_rn(y - __bfloat162float(hy)));
}

// fast exp via degree-5 exp2 polynomial (FMA pipe, no MUFU); rel err ~1e-7
static __device__ __forceinline__ float fast_exp(float x) {
    float t = x * 1.4426950408889634f;
    float r = rintf(t);
    float f = t - r;
    float p = 1.33336498e-3f;
    p = fmaf(p, f, 9.61597636e-3f);
    p = fmaf(p, f, 5.55036440e-2f);
    p = fmaf(p, f, 2.40226462e-1f);
    p = fmaf(p, f, 6.93147182e-1f);
    p = fmaf(p, f, 1.0f);
    int e = (int)r;
    e = e < -126 ? -126 : e;
    return p * __int_as_float((e + 127) << 23);
}

// ---------------- GEMM core: C[128,128] = A[128,K]*B[128,K]^T, bf16x3 fp32-emulated ----
// Pre-split bf16 hi/lo planes in gmem, K-contiguous. KTILE=64, XOR-swizzled 128B smem
// rows, NS=3 triple buffer: steady-state wait_group<1> gives each cp.async ~2 compute
// phases of latency budget. 1 __syncthreads per k-tile.
#define KTILE   64
#define PLANE_B 16384                 // 128 rows x 128 B
#define STAGE_B (4 * PLANE_B)         // Ahi, Alo, Bhi, Blo
#define NSTAGE  3
#define SMEM_DYN (NSTAGE * STAGE_B)   // 196608 B

static __device__ __forceinline__ void issue_stage(
    const bf16* __restrict__ Ahi, const bf16* __restrict__ Alo, size_t lda,
    const bf16* __restrict__ Bhi, const bf16* __restrict__ Blo, size_t ldb,
    int k0, uint32_t sb, int tid) {
#pragma unroll
    for (int pl = 0; pl < 4; pl++) {
        const bf16* g = (pl == 0) ? Ahi : (pl == 1) ? Alo : (pl == 2) ? Bhi : Blo;
        const size_t ld = (pl < 2) ? lda : ldb;
        const uint32_t pb = sb + pl * PLANE_B;
#pragma unroll
        for (int j = 0; j < 4; j++) {
            int idx = j * 256 + tid;         // 0..1023 chunks per plane
            int row = idx >> 3;              // 128 rows
            int ch  = idx & 7;               // 8 x 16B chunks per 128B row
            cp16(pb + row * 128 + ((ch ^ (row & 7)) << 4),
                 g + (size_t)row * ld + k0 + ch * 8);
        }
    }
    cp_commit();
}

static __device__ void gemm_core(
    const bf16* __restrict__ Ahi, const bf16* __restrict__ Alo, size_t lda,
    const bf16* __restrict__ Bhi, const bf16* __restrict__ Blo, size_t ldb,
    int n, char* sm, float acc[4][4][4]) {
    const int tid  = threadIdx.x;
    const int lane = tid & 31;
    const int warp = tid >> 5;
    const int mbase = (warp >> 2) * 64;     // 2 warps in M
    const int nbase = (warp & 3) * 32;      // 4 warps in N
    const uint32_t s0 = smem_u32(sm);

    const uint32_t sw    = (uint32_t)(lane & 7);        // XOR swizzle key
    const uint32_t a_row = (uint32_t)(mbase + (lane & 15));
    const uint32_t a_hb  = (uint32_t)(lane >> 4);       // k-half select for ldm_x4
    const uint32_t b_row = (uint32_t)(nbase + (lane & 7));
    const uint32_t b_hb  = (uint32_t)((lane >> 3) & 1); // k-half select for ldm_x2

    issue_stage(Ahi, Alo, lda, Bhi, Blo, ldb, 0, s0, tid);
    if (n > 1)
        issue_stage(Ahi, Alo, lda, Bhi, Blo, ldb, KTILE, s0 + STAGE_B, tid);

    for (int it = 0; it < n; ++it) {
        if (it + 1 < n) cp_wait<1>();   // oldest group (stage it) landed
        else            cp_wait<0>();   // last tile: everything landed
        __syncthreads();
        if (it + 2 < n)                 // slot (it+2)%3 was consumed at iter it-1
            issue_stage(Ahi, Alo, lda, Bhi, Blo, ldb, (it + 2) * KTILE,
                        s0 + (uint32_t)((it + 2) % NSTAGE) * STAGE_B, tid);
        const uint32_t st = s0 + (uint32_t)(it % NSTAGE) * STAGE_B;
#pragma unroll
        for (int kk = 0; kk < 4; ++kk) {
            uint32_t bh[4][2], bl[4][2];
            const uint32_t bch = (uint32_t)kk * 2 + b_hb;
            const uint32_t bsw = (bch ^ sw) << 4;
#pragma unroll
            for (int in = 0; in < 4; in++) {
                uint32_t off = (b_row + in * 8) * 128 + bsw;
                ldm_x2(bh[in], st + 2 * PLANE_B + off);
                ldm_x2(bl[in], st + 3 * PLANE_B + off);
            }
            const uint32_t ach = (uint32_t)kk * 2 + a_hb;
            const uint32_t asw = (ach ^ sw) << 4;
#pragma unroll
            for (int im = 0; im < 4; im++) {
                uint32_t off = (a_row + im * 16) * 128 + asw;
                uint32_t ah[4], al[4];
                ldm_x4(ah, st + 0 * PLANE_B + off);
                ldm_x4(al, st + 1 * PLANE_B + off);
#pragma unroll
                for (int in = 0; in < 4; in++) {
                    mma_bf16(acc[im][in], ah, bh[in]);   // hi*hi
                    mma_bf16(acc[im][in], ah, bl[in]);   // hi*lo
                    mma_bf16(acc[im][in], al, bh[in]);   // lo*hi
                }
            }
        }
    }
    __syncthreads();   // smem safe for epilogue reuse
}

#define ZERO_ACC(acc) do {                                   \
    _Pragma("unroll") for (int _i = 0; _i < 4; _i++)         \
    _Pragma("unroll") for (int _j = 0; _j < 4; _j++)         \
    _Pragma("unroll") for (int _r = 0; _r < 4; _r++)         \
        acc[_i][_j][_r] = 0.0f;                              \
} while (0)

// ---------------- Stage 0: fp32 -> bf16 hi/lo plane conversion ----------------
__global__ __launch_bounds__(256) void cvt_kernel(const float4* __restrict__ src,
                                                  bf162* __restrict__ hi,
                                                  bf162* __restrict__ lo, int n4) {
    int i = blockIdx.x * blockDim.x + threadIdx.x;
    if (i < n4) {
        float4 f = src[i];
        bf162 h0, l0, h1, l1;
        split2(f.x, f.y, h0, l0);
        split2(f.z, f.w, h1, l1);
        hi[i * 2] = h0; hi[i * 2 + 1] = h1;
        lo[i * 2] = l0; lo[i * 2 + 1] = l1;
    }
}

// merged W conversion: z selects Wq/Wk/Wv, writes into the packed 3*H*H planes
__global__ __launch_bounds__(256) void cvt_w_kernel(const float4* __restrict__ Wq,
                                                    const float4* __restrict__ Wk,
                                                    const float4* __restrict__ Wv,
                                                    bf162* __restrict__ hi,
                                                    bf162* __restrict__ lo, int n4) {
    int i = blockIdx.x * blockDim.x + threadIdx.x;
    if (i >= n4) return;
    const int z = blockIdx.z;
    const float4* src = (z == 0) ? Wq : (z == 1) ? Wk : Wv;
    bf162* h = hi + (size_t)z * n4 * 2;
    bf162* l = lo + (size_t)z * n4 * 2;
    float4 f = src[i];
    bf162 h0, l0, h1, l1;
    split2(f.x, f.y, h0, l0);
    split2(f.z, f.w, h1, l1);
    h[i * 2] = h0; h[i * 2 + 1] = h1;
    l[i * 2] = l0; l[i * 2 + 1] = l1;
}

// ---------------- Stage 1: fused QKV projection ----------------
// grid = (8, 64, 3). z selects {q,k,v}. v transposed via smem -> coalesced plane stores.
__global__ __launch_bounds__(256, 1) void qkv_kernel(const float* __restrict__ bq,
                                                     const float* __restrict__ bk,
                                                     const float* __restrict__ bv) {
    extern __shared__ char sm[];
    const int z = blockIdx.z, bm = blockIdx.y, bn = blockIdx.x;
    const float* bias = (z == 0) ? bq : ((z == 1) ? bk : bv);

    float acc[4][4][4];
    ZERO_ACC(acc);
    gemm_core(g_xhi + (size_t)bm * 128 * HH, g_xlo + (size_t)bm * 128 * HH, HH,
              g_whi + (size_t)z * HH * HH + (size_t)bn * 128 * HH,
              g_wlo + (size_t)z * HH * HH + (size_t)bn * 128 * HH, HH,
              HH / KTILE, sm, acc);

    const int lane = threadIdx.x & 31;
    const int warp = threadIdx.x >> 5;
    const int mbase = (warp >> 2) * 64;
    const int nbase = (warp & 3) * 32;
    const int gr = lane >> 2;
    const int gc = (lane & 3) << 1;

    if (z < 2) {
        bf16* ohi = (z == 0) ? g_qhi : g_khi;
        bf16* olo = (z == 0) ? g_qlo : g_klo;
#pragma unroll
        for (int im = 0; im < 4; im++) {
#pragma unroll
            for (int in = 0; in < 4; in++) {
                int row = bm * 128 + mbase + im * 16 + gr;
                int col = bn * 128 + nbase + in * 8 + gc;
                float b0 = bias[col], b1 = bias[col + 1];
                bf162 h2, l2;
                split2(acc[im][in][0] + b0, acc[im][in][1] + b1, h2, l2);
                *reinterpret_cast<bf162*>(&ohi[(size_t)row * HH + col]) = h2;
                *reinterpret_cast<bf162*>(&olo[(size_t)row * HH + col]) = l2;
                split2(acc[im][in][2] + b0, acc[im][in][3] + b1, h2, l2);
                *reinterpret_cast<bf162*>(&ohi[(size_t)(row + 8) * HH + col]) = h2;
                *reinterpret_cast<bf162*>(&olo[(size_t)(row + 8) * HH + col]) = l2;
            }
        }
    } else {
        // transpose v tile through smem, then coalesced hi/lo stores into [b][h][s] planes
        float* ts = reinterpret_cast<float*>(sm);   // 128 x 129 fp32 = 66048 B <= SMEM_DYN
#pragma unroll
        for (int im = 0; im < 4; im++) {
#pragma unroll
            for (int in = 0; in < 4; in++) {
                int r0 = mbase + im * 16 + gr;
                int c0 = nbase + in * 8 + gc;
                float b0 = bias[bn * 128 + c0], b1 = bias[bn * 128 + c0 + 1];
                ts[r0 * 129 + c0]           = acc[im][in][0] + b0;
                ts[r0 * 129 + c0 + 1]       = acc[im][in][1] + b1;
                ts[(r0 + 8) * 129 + c0]     = acc[im][in][2] + b0;
                ts[(r0 + 8) * 129 + c0 + 1] = acc[im][in][3] + b1;
            }
        }
        __syncthreads();
        const int b = (bm * 128) >> 11;
        const int sbase = (bm * 128) & (SS - 1);
#pragma unroll
        for (int hr = 0; hr < 16; hr++) {
            int hl = warp * 16 + hr;                         // local h row 0..127
            size_t obase = ((size_t)b * HH + bn * 128 + hl) * SS + sbase;
#pragma unroll
            for (int pass = 0; pass < 2; pass++) {
                int sl = pass * 64 + lane * 2;
                bf162 h2, l2;
                split2(ts[sl * 129 + hl], ts[(sl + 1) * 129 + hl], h2, l2);
                *reinterpret_cast<bf162*>(&g_vthi[obase + sl]) = h2;
                *reinterpret_cast<bf162*>(&g_vtlo[obase + sl]) = l2;
            }
        }
    }
}

// ---------------- Stage 2: scores = q k^T * scale + attn_mask + pw*prosody ----------
__global__ __launch_bounds__(256, 1) void scores_kernel(const float* __restrict__ am,
                                                        const float* __restrict__ pm,
                                                        const float* __restrict__ pwp) {
    extern __shared__ char sm[];
    const int b = blockIdx.z, bm = blockIdx.y, bn = blockIdx.x;

    float acc[4][4][4];
    ZERO_ACC(acc);
    const size_t ao = ((size_t)b * SS + bm * 128) * HH;
    const size_t bo = ((size_t)b * SS + bn * 128) * HH;
    gemm_core(g_qhi + ao, g_qlo + ao, HH, g_khi + bo, g_klo + bo, HH,
              HH / KTILE, sm, acc);

    const float pw = __ldg(pwp);
    const float scale = 0.03125f;   // 1/sqrt(1024)
    const int lane = threadIdx.x & 31;
    const int warp = threadIdx.x >> 5;
    const int mbase = (warp >> 2) * 64;
    const int nbase = (warp & 3) * 32;
    const int gr = lane >> 2;
    const int gc = (lane & 3) << 1;

#pragma unroll
    for (int im = 0; im < 4; im++) {
#pragma unroll
        for (int in = 0; in < 4; in++) {
            int row = bm * 128 + mbase + im * 16 + gr;
            int col = bn * 128 + nbase + in * 8 + gc;
#pragma unroll
            for (int half = 0; half < 2; half++) {
                int r = row + half * 8;
                size_t off = ((size_t)b * SS + r) * SS + col;
                float2 amv = *reinterpret_cast<const float2*>(&am[off]);
                float2 pmv = *reinterpret_cast<const float2*>(&pm[off]);
                float v0 = fmaf(acc[im][in][half * 2 + 0], scale, fmaf(pw, pmv.x, amv.x));
                float v1 = fmaf(acc[im][in][half * 2 + 1], scale, fmaf(pw, pmv.y, amv.y));
                *reinterpret_cast<float2*>(&g_s[off]) = make_float2(v0, v1);
            }
        }
    }
}

// ---------------- Stage 3: row softmax -> bf16 hi/lo prob planes ----------------
__global__ __launch_bounds__(256) void softmax_kernel() {
    const size_t rid = blockIdx.x;
    const float* row = g_s + rid * SS;
    const int tid = threadIdx.x;
    const int lane = tid & 31;
    const int warp = tid >> 5;
    const float4* rv = reinterpret_cast<const float4*>(row);
    float4 a = rv[tid];
    float4 c = rv[tid + 256];

    float m = fmaxf(fmaxf(fmaxf(a.x, a.y), fmaxf(a.z, a.w)),
                    fmaxf(fmaxf(c.x, c.y), fmaxf(c.z, c.w)));
#pragma unroll
    for (int o = 16; o > 0; o >>= 1) m = fmaxf(m, __shfl_xor_sync(0xffffffffu, m, o));
    __shared__ float smax[8], ssum[8];
    if (lane == 0) smax[warp] = m;
    __syncthreads();
    m = smax[0];
#pragma unroll
    for (int w = 1; w < 8; w++) m = fmaxf(m, smax[w]);

    a.x = fast_exp(a.x - m); a.y = fast_exp(a.y - m);
    a.z = fast_exp(a.z - m); a.w = fast_exp(a.w - m);
    c.x = fast_exp(c.x - m); c.y = fast_exp(c.y - m);
    c.z = fast_exp(c.z - m); c.w = fast_exp(c.w - m);
    float s = a.x + a.y + a.z + a.w + c.x + c.y + c.z + c.w;
#pragma unroll
    for (int o = 16; o > 0; o >>= 1) s += __shfl_xor_sync(0xffffffffu, s, o);
    if (lane == 0) ssum[warp] = s;
    __syncthreads();
    s = ssum[0];
#pragma unroll
    for (int w = 1; w < 8; w++) s += ssum[w];
    const float inv = 1.0f / s;

    bf162* ph = reinterpret_cast<bf162*>(g_phi);
    bf162* pl = reinterpret_cast<bf162*>(g_plo);
    size_t base = rid * (SS / 2) + tid * 2;
    bf162 h2, l2;
    split2(a.x * inv, a.y * inv, h2, l2); ph[base] = h2;       pl[base] = l2;
    split2(a.z * inv, a.w * inv, h2, l2); ph[base + 1] = h2;   pl[base + 1] = l2;
    split2(c.x * inv, c.y * inv, h2, l2); ph[base + 512] = h2; pl[base + 512] = l2;
    split2(c.z * inv, c.w * inv, h2, l2); ph[base + 513] = h2; pl[base + 513] = l2;
}

// ---------------- Stage 4: context = probs @ v ----------------
__global__ __launch_bounds__(256, 1) void pv_kernel(float* __restrict__ out) {
    extern __shared__ char sm[];
    const int b = blockIdx.z, bm = blockIdx.y, bn = blockIdx.x;

    float acc[4][4][4];
    ZERO_ACC(acc);
    const size_t ao = ((size_t)b * SS + bm * 128) * SS;
    const size_t bo = ((size_t)b * HH + bn * 128) * SS;
    gemm_core(g_phi + ao, g_plo + ao, SS, g_vthi + bo, g_vtlo + bo, SS,
              SS / KTILE, sm, acc);

    const int lane = threadIdx.x & 31;
    const int warp = threadIdx.x >> 5;
    const int mbase = (warp >> 2) * 64;
    const int nbase = (warp & 3) * 32;
    const int gr = lane >> 2;
    const int gc = (lane & 3) << 1;

#pragma unroll
    for (int im = 0; im < 4; im++) {
#pragma unroll
        for (int in = 0; in < 4; in++) {
            int row = bm * 128 + mbase + im * 16 + gr;
            int col = bn * 128 + nbase + in * 8 + gc;
            size_t o0 = ((size_t)b * SS + row) * HH + col;
            size_t o1 = ((size_t)b * SS + row + 8) * HH + col;
            *reinterpret_cast<float2*>(&out[o0]) = make_float2(acc[im][in][0], acc[im][in][1]);
            *reinterpret_cast<float2*>(&out[o1]) = make_float2(acc[im][in][2], acc[im][in][3]);
        }
    }
}

// ---------------- launch ----------------
extern "C" void kernel_launch(void* const* d_in, const int* in_sizes, int n_in,
                              void* d_out, int out_size) {
    (void)in_sizes; (void)n_in; (void)out_size;
    const float* X  = (const float*)d_in[0];
    const float* am = (const float*)d_in[1];
    const float* pm = (const float*)d_in[2];
    const float* Wq = (const float*)d_in[3];
    const float* bq = (const float*)d_in[4];
    const float* Wk = (const float*)d_in[5];
    const float* bk = (const float*)d_in[6];
    const float* Wv = (const float*)d_in[7];
    const float* bv = (const float*)d_in[8];
    const float* pw = (const float*)d_in[9];
    float* out = (float*)d_out;

    cudaFuncSetAttribute(qkv_kernel,    cudaFuncAttributeMaxDynamicSharedMemorySize, SMEM_DYN);
    cudaFuncSetAttribute(scores_kernel, cudaFuncAttributeMaxDynamicSharedMemorySize, SMEM_DYN);
    cudaFuncSetAttribute(pv_kernel,     cudaFuncAttributeMaxDynamicSharedMemorySize, SMEM_DYN);

    {
        bf162 *xhi2, *xlo2, *whi2, *wlo2;
        cudaGetSymbolAddress((void**)&xhi2, g_xhi);
        cudaGetSymbolAddress((void**)&xlo2, g_xlo);
        cudaGetSymbolAddress((void**)&whi2, g_whi);
        cudaGetSymbolAddress((void**)&wlo2, g_wlo);
        int n4 = (BB * SS * HH) / 4;
        cvt_kernel<<<(n4 + 255) / 256, 256>>>((const float4*)X, xhi2, xlo2, n4);
        int w4 = (HH * HH) / 4;
        cvt_w_kernel<<<dim3((w4 + 255) / 256, 1, 3), 256>>>(
            (const float4*)Wq, (const float4*)Wk, (const float4*)Wv, whi2, wlo2, w4);
    }

    qkv_kernel<<<dim3(HH / 128, (BB * SS) / 128, 3), 256, SMEM_DYN>>>(bq, bk, bv);
    scores_kernel<<<dim3(SS / 128, SS / 128, BB), 256, SMEM_DYN>>>(am, pm, pw);
    softmax_kernel<<<BB * SS, 256>>>();
    pv_kernel<<<dim3(HH / 128, SS / 128, BB), 256, SMEM_DYN>>>(out);
}

// round 14
// speedup vs baseline: 1.0143x; 1.0143x over previous
#include <cuda_runtime.h>
#include <cuda_bf16.h>
#include <cstdint>

#define BB 4
#define SS 2048
#define HH 1024

typedef __nv_bfloat16  bf16;
typedef __nv_bfloat162 bf162;

// ---------------- scratch (static device globals; no allocation) ----------------
__device__ __align__(256) bf16 g_xhi[(size_t)BB*SS*HH], g_xlo[(size_t)BB*SS*HH];
__device__ __align__(256) bf16 g_whi[(size_t)3*HH*HH],  g_wlo[(size_t)3*HH*HH];
__device__ __align__(256) bf16 g_qhi[(size_t)BB*SS*HH], g_qlo[(size_t)BB*SS*HH];
__device__ __align__(256) bf16 g_khi[(size_t)BB*SS*HH], g_klo[(size_t)BB*SS*HH];
__device__ __align__(256) bf16 g_vthi[(size_t)BB*HH*SS],g_vtlo[(size_t)BB*HH*SS];
__device__ __align__(256) float g_s[(size_t)BB*SS*SS];
__device__ __align__(256) bf16 g_phi[(size_t)BB*SS*SS], g_plo[(size_t)BB*SS*SS];

// ---------------- low-level helpers ----------------
// NOTE: not volatile — register-only op; lets the compiler interleave LDSM with HMMA.
static __device__ __forceinline__ void mma_bf16(float* d, const uint32_t* a, const uint32_t* b) {
    asm("mma.sync.aligned.m16n8k16.row.col.f32.bf16.bf16.f32 "
        "{%0,%1,%2,%3}, {%4,%5,%6,%7}, {%8,%9}, {%0,%1,%2,%3};\n"
        : "+f"(d[0]), "+f"(d[1]), "+f"(d[2]), "+f"(d[3])
        : "r"(a[0]), "r"(a[1]), "r"(a[2]), "r"(a[3]), "r"(b[0]), "r"(b[1]));
}

static __device__ __forceinline__ uint32_t smem_u32(const void* p) {
    return (uint32_t)__cvta_generic_to_shared(p);
}
static __device__ __forceinline__ void cp16(uint32_t dst, const void* src) {
    asm volatile("cp.async.cg.shared.global [%0], [%1], 16;\n" :: "r"(dst), "l"(src));
}
static __device__ __forceinline__ void cp_commit() { asm volatile("cp.async.commit_group;\n"); }
template <int N>
static __device__ __forceinline__ void cp_wait() {
    asm volatile("cp.async.wait_group %0;\n" :: "n"(N));
}
static __device__ __forceinline__ void ldm_x4(uint32_t* r, uint32_t addr) {
    asm volatile("ldmatrix.sync.aligned.m8n8.x4.shared.b16 {%0,%1,%2,%3}, [%4];\n"
        : "=r"(r[0]), "=r"(r[1]), "=r"(r[2]), "=r"(r[3]) : "r"(addr));
}
static __device__ __forceinline__ void ldm_x2(uint32_t* r, uint32_t addr) {
    asm volatile("ldmatrix.sync.aligned.m8n8.x2.shared.b16 {%0,%1}, [%2];\n"
        : "=r"(r[0]), "=r"(r[1]) : "r"(addr));
}

static __device__ __forceinline__ void split2(float x, float y, bf162& h2, bf162& l2) {
    bf16 hx = __float2bfloat16_rn(x);
    bf16 hy = __float2bfloat16_rn(y);
    h2 = __halves2bfloat162(hx, hy);
    l2 = __halves2bfloat162(__float2bfloat16_rn(x - __bfloat162float(hx)),
                            __float2bfloat16_rn(y - __bfloat162float(hy)));
}

// fast exp via degree-5 exp2 polynomial (FMA pipe, no MUFU); rel err ~1e-7
static __device__ __forceinline__ float fast_exp(float x) {
    float t = x * 1.4426950408889634f;
    float r = rintf(t);
    float f = t - r;
    float p = 1.33336498e-3f;
    p = fmaf(p, f, 9.61597636e-3f);
    p = fmaf(p, f, 5.55036440e-2f);
    p = fmaf(p, f, 2.40226462e-1f);
    p = fmaf(p, f, 6.93147182e-1f);
    p = fmaf(p, f, 1.0f);
    int e = (int)r;
    e = e < -126 ? -126 : e;
    return p * __int_as_float((e + 127) << 23);
}

// ---------------- GEMM core: C[128,128] = A[128,K]*B[128,K]^T, bf16x3 fp32-emulated ----
// Pre-split bf16 hi/lo planes in gmem, K-contiguous. KTILE=64, XOR-swizzled 128B smem
// rows, NS=2 double buffer, 1 sync/tile. Per kk-step: load ALL fragments, then issue
// the 48 MMAs in three 16-wide passes so same-accumulator MMAs are 16 apart.
#define KTILE   64
#define PLANE_B 16384                 // 128 rows x 128 B
#define STAGE_B (4 * PLANE_B)         // Ahi, Alo, Bhi, Blo
#define SMEM_DYN (2 * STAGE_B)        // 131072 B

static __device__ __forceinline__ void issue_stage(
    const bf16* __restrict__ Ahi, const bf16* __restrict__ Alo, size_t lda,
    const bf16* __restrict__ Bhi, const bf16* __restrict__ Blo, size_t ldb,
    int k0, uint32_t sb, int tid) {
#pragma unroll
    for (int pl = 0; pl < 4; pl++) {
        const bf16* g = (pl == 0) ? Ahi : (pl == 1) ? Alo : (pl == 2) ? Bhi : Blo;
        const size_t ld = (pl < 2) ? lda : ldb;
        const uint32_t pb = sb + pl * PLANE_B;
#pragma unroll
        for (int j = 0; j < 4; j++) {
            int idx = j * 256 + tid;         // 0..1023 chunks per plane
            int row = idx >> 3;              // 128 rows
            int ch  = idx & 7;               // 8 x 16B chunks per 128B row
            cp16(pb + row * 128 + ((ch ^ (row & 7)) << 4),
                 g + (size_t)row * ld + k0 + ch * 8);
        }
    }
    cp_commit();
}

static __device__ void gemm_core(
    const bf16* __restrict__ Ahi, const bf16* __restrict__ Alo, size_t lda,
    const bf16* __restrict__ Bhi, const bf16* __restrict__ Blo, size_t ldb,
    int n, char* sm, float acc[4][4][4]) {
    const int tid  = threadIdx.x;
    const int lane = tid & 31;
    const int warp = tid >> 5;
    const int mbase = (warp >> 2) * 64;     // 2 warps in M
    const int nbase = (warp & 3) * 32;      // 4 warps in N
    const uint32_t s0 = smem_u32(sm);

    const uint32_t sw    = (uint32_t)(lane & 7);        // XOR swizzle key
    const uint32_t a_row = (uint32_t)(mbase + (lane & 15));
    const uint32_t a_hb  = (uint32_t)(lane >> 4);       // k-half select for ldm_x4
    const uint32_t b_row = (uint32_t)(nbase + (lane & 7));
    const uint32_t b_hb  = (uint32_t)((lane >> 3) & 1); // k-half select for ldm_x2

    issue_stage(Ahi, Alo, lda, Bhi, Blo, ldb, 0, s0, tid);

    for (int it = 0; it < n; ++it) {
        cp_wait<0>();
        __syncthreads();
        if (it + 1 < n)
            issue_stage(Ahi, Alo, lda, Bhi, Blo, ldb, (it + 1) * KTILE,
                        s0 + (uint32_t)((it + 1) & 1) * STAGE_B, tid);
        const uint32_t st = s0 + (uint32_t)(it & 1) * STAGE_B;
#pragma unroll
        for (int kk = 0; kk < 4; ++kk) {
            uint32_t bh[4][2], bl[4][2], ah[4][4], al[4][4];
            const uint32_t bch = (uint32_t)kk * 2 + b_hb;
            const uint32_t bsw = (bch ^ sw) << 4;
#pragma unroll
            for (int in = 0; in < 4; in++) {
                uint32_t off = (b_row + in * 8) * 128 + bsw;
                ldm_x2(bh[in], st + 2 * PLANE_B + off);
                ldm_x2(bl[in], st + 3 * PLANE_B + off);
            }
            const uint32_t ach = (uint32_t)kk * 2 + a_hb;
            const uint32_t asw = (ach ^ sw) << 4;
#pragma unroll
            for (int im = 0; im < 4; im++) {
                uint32_t off = (a_row + im * 16) * 128 + asw;
                ldm_x4(ah[im], st + 0 * PLANE_B + off);
                ldm_x4(al[im], st + 1 * PLANE_B + off);
            }
            // three 16-MMA passes: same-acc dependency distance = 16
#pragma unroll
            for (int im = 0; im < 4; im++)
#pragma unroll
                for (int in = 0; in < 4; in++)
                    mma_bf16(acc[im][in], ah[im], bh[in]);   // hi*hi
#pragma unroll
            for (int im = 0; im < 4; im++)
#pragma unroll
                for (int in = 0; in < 4; in++)
                    mma_bf16(acc[im][in], ah[im], bl[in]);   // hi*lo
#pragma unroll
            for (int im = 0; im < 4; im++)
#pragma unroll
                for (int in = 0; in < 4; in++)
                    mma_bf16(acc[im][in], al[im], bh[in]);   // lo*hi
        }
    }
    __syncthreads();   // smem safe for epilogue reuse
}

#define ZERO_ACC(acc) do {                                   \
    _Pragma("unroll") for (int _i = 0; _i < 4; _i++)         \
    _Pragma("unroll") for (int _j = 0; _j < 4; _j++)         \
    _Pragma("unroll") for (int _r = 0; _r < 4; _r++)         \
        acc[_i][_j][_r] = 0.0f;                              \
} while (0)

// ---------------- Stage 0: fp32 -> bf16 hi/lo plane conversion ----------------
__global__ __launch_bounds__(256) void cvt_kernel(const float4* __restrict__ src,
                                                  bf162* __restrict__ hi,
                                                  bf162* __restrict__ lo, int n4) {
    int i = blockIdx.x * blockDim.x + threadIdx.x;
    if (i < n4) {
        float4 f = src[i];
        bf162 h0, l0, h1, l1;
        split2(f.x, f.y, h0, l0);
        split2(f.z, f.w, h1, l1);
        hi[i * 2] = h0; hi[i * 2 + 1] = h1;
        lo[i * 2] = l0; lo[i * 2 + 1] = l1;
    }
}

// merged W conversion: z selects Wq/Wk/Wv, writes into the packed 3*H*H planes
__global__ __launch_bounds__(256) void cvt_w_kernel(const float4* __restrict__ Wq,
                                                    const float4* __restrict__ Wk,
                                                    const float4* __restrict__ Wv,
                                                    bf162* __restrict__ hi,
                                                    bf162* __restrict__ lo, int n4) {
    int i = blockIdx.x * blockDim.x + threadIdx.x;
    if (i >= n4) return;
    const int z = blockIdx.z;
    const float4* src = (z == 0) ? Wq : (z == 1) ? Wk : Wv;
    bf162* h = hi + (size_t)z * n4 * 2;
    bf162* l = lo + (size_t)z * n4 * 2;
    float4 f = src[i];
    bf162 h0, l0, h1, l1;
    split2(f.x, f.y, h0, l0);
    split2(f.z, f.w, h1, l1);
    h[i * 2] = h0; h[i * 2 + 1] = h1;
    l[i * 2] = l0; l[i * 2 + 1] = l1;
}

// ---------------- Stage 1: fused QKV projection ----------------
// grid = (8, 64, 3). z selects {q,k,v}. v transposed via smem -> coalesced plane stores.
__global__ __launch_bounds__(256, 1) void qkv_kernel(const float* __restrict__ bq,
                                                     const float* __restrict__ bk,
                                                     const float* __restrict__ bv) {
    extern __shared__ char sm[];
    const int z = blockIdx.z, bm = blockIdx.y, bn = blockIdx.x;
    const float* bias = (z == 0) ? bq : ((z == 1) ? bk : bv);

    float acc[4][4][4];
    ZERO_ACC(acc);
    gemm_core(g_xhi + (size_t)bm * 128 * HH, g_xlo + (size_t)bm * 128 * HH, HH,
              g_whi + (size_t)z * HH * HH + (size_t)bn * 128 * HH,
              g_wlo + (size_t)z * HH * HH + (size_t)bn * 128 * HH, HH,
              HH / KTILE, sm, acc);

    const int lane = threadIdx.x & 31;
    const int warp = threadIdx.x >> 5;
    const int mbase = (warp >> 2) * 64;
    const int nbase = (warp & 3) * 32;
    const int gr = lane >> 2;
    const int gc = (lane & 3) << 1;

    if (z < 2) {
        bf16* ohi = (z == 0) ? g_qhi : g_khi;
        bf16* olo = (z == 0) ? g_qlo : g_klo;
#pragma unroll
        for (int im = 0; im < 4; im++) {
#pragma unroll
            for (int in = 0; in < 4; in++) {
                int row = bm * 128 + mbase + im * 16 + gr;
                int col = bn * 128 + nbase + in * 8 + gc;
                float b0 = bias[col], b1 = bias[col + 1];
                bf162 h2, l2;
                split2(acc[im][in][0] + b0, acc[im][in][1] + b1, h2, l2);
                *reinterpret_cast<bf162*>(&ohi[(size_t)row * HH + col]) = h2;
                *reinterpret_cast<bf162*>(&olo[(size_t)row * HH + col]) = l2;
                split2(acc[im][in][2] + b0, acc[im][in][3] + b1, h2, l2);
                *reinterpret_cast<bf162*>(&ohi[(size_t)(row + 8) * HH + col]) = h2;
                *reinterpret_cast<bf162*>(&olo[(size_t)(row + 8) * HH + col]) = l2;
            }
        }
    } else {
        // transpose v tile through smem, then coalesced hi/lo stores into [b][h][s] planes
        float* ts = reinterpret_cast<float*>(sm);   // 128 x 129 fp32 = 66048 B <= SMEM_DYN
#pragma unroll
        for (int im = 0; im < 4; im++) {
#pragma unroll
            for (int in = 0; in < 4; in++) {
                int r0 = mbase + im * 16 + gr;
                int c0 = nbase + in * 8 + gc;
                float b0 = bias[bn * 128 + c0], b1 = bias[bn * 128 + c0 + 1];
                ts[r0 * 129 + c0]           = acc[im][in][0] + b0;
                ts[r0 * 129 + c0 + 1]       = acc[im][in][1] + b1;
                ts[(r0 + 8) * 129 + c0]     = acc[im][in][2] + b0;
                ts[(r0 + 8) * 129 + c0 + 1] = acc[im][in][3] + b1;
            }
        }
        __syncthreads();
        const int b = (bm * 128) >> 11;
        const int sbase = (bm * 128) & (SS - 1);
#pragma unroll
        for (int hr = 0; hr < 16; hr++) {
            int hl = warp * 16 + hr;                         // local h row 0..127
            size_t obase = ((size_t)b * HH + bn * 128 + hl) * SS + sbase;
#pragma unroll
            for (int pass = 0; pass < 2; pass++) {
                int sl = pass * 64 + lane * 2;
                bf162 h2, l2;
                split2(ts[sl * 129 + hl], ts[(sl + 1) * 129 + hl], h2, l2);
                *reinterpret_cast<bf162*>(&g_vthi[obase + sl]) = h2;
                *reinterpret_cast<bf162*>(&g_vtlo[obase + sl]) = l2;
            }
        }
    }
}

// ---------------- Stage 2: scores = q k^T * scale + attn_mask + pw*prosody ----------
__global__ __launch_bounds__(256, 1) void scores_kernel(const float* __restrict__ am,
                                                        const float* __restrict__ pm,
                                                        const float* __restrict__ pwp) {
    extern __shared__ char sm[];
    const int b = blockIdx.z, bm = blockIdx.y, bn = blockIdx.x;

    float acc[4][4][4];
    ZERO_ACC(acc);
    const size_t ao = ((size_t)b * SS + bm * 128) * HH;
    const size_t bo = ((size_t)b * SS + bn * 128) * HH;
    gemm_core(g_qhi + ao, g_qlo + ao, HH, g_khi + bo, g_klo + bo, HH,
              HH / KTILE, sm, acc);

    const float pw = __ldg(pwp);
    const float scale = 0.03125f;   // 1/sqrt(1024)
    const int lane = threadIdx.x & 31;
    const int warp = threadIdx.x >> 5;
    const int mbase = (warp >> 2) * 64;
    const int nbase = (warp & 3) * 32;
    const int gr = lane >> 2;
    const int gc = (lane & 3) << 1;

#pragma unroll
    for (int im = 0; im < 4; im++) {
#pragma unroll
        for (int in = 0; in < 4; in++) {
            int row = bm * 128 + mbase + im * 16 + gr;
            int col = bn * 128 + nbase + in * 8 + gc;
#pragma unroll
            for (int half = 0; half < 2; half++) {
                int r = row + half * 8;
                size_t off = ((size_t)b * SS + r) * SS + col;
                float2 amv = *reinterpret_cast<const float2*>(&am[off]);
                float2 pmv = *reinterpret_cast<const float2*>(&pm[off]);
                float v0 = fmaf(acc[im][in][half * 2 + 0], scale, fmaf(pw, pmv.x, amv.x));
                float v1 = fmaf(acc[im][in][half * 2 + 1], scale, fmaf(pw, pmv.y, amv.y));
                *reinterpret_cast<float2*>(&g_s[off]) = make_float2(v0, v1);
            }
        }
    }
}

// ---------------- Stage 3: row softmax -> bf16 hi/lo prob planes ----------------
__global__ __launch_bounds__(256) void softmax_kernel() {
    const size_t rid = blockIdx.x;
    const float* row = g_s + rid * SS;
    const int tid = threadIdx.x;
    const int lane = tid & 31;
    const int warp = tid >> 5;
    const float4* rv = reinterpret_cast<const float4*>(row);
    float4 a = rv[tid];
    float4 c = rv[tid + 256];

    float m = fmaxf(fmaxf(fmaxf(a.x, a.y), fmaxf(a.z, a.w)),
                    fmaxf(fmaxf(c.x, c.y), fmaxf(c.z, c.w)));
#pragma unroll
    for (int o = 16; o > 0; o >>= 1) m = fmaxf(m, __shfl_xor_sync(0xffffffffu, m, o));
    __shared__ float smax[8], ssum[8];
    if (lane == 0) smax[warp] = m;
    __syncthreads();
    m = smax[0];
#pragma unroll
    for (int w = 1; w < 8; w++) m = fmaxf(m, smax[w]);

    a.x = fast_exp(a.x - m); a.y = fast_exp(a.y - m);
    a.z = fast_exp(a.z - m); a.w = fast_exp(a.w - m);
    c.x = fast_exp(c.x - m); c.y = fast_exp(c.y - m);
    c.z = fast_exp(c.z - m); c.w = fast_exp(c.w - m);
    float s = a.x + a.y + a.z + a.w + c.x + c.y + c.z + c.w;
#pragma unroll
    for (int o = 16; o > 0; o >>= 1) s += __shfl_xor_sync(0xffffffffu, s, o);
    if (lane == 0) ssum[warp] = s;
    __syncthreads();
    s = ssum[0];
#pragma unroll
    for (int w = 1; w < 8; w++) s += ssum[w];
    const float inv = 1.0f / s;

    bf162* ph = reinterpret_cast<bf162*>(g_phi);
    bf162* pl = reinterpret_cast<bf162*>(g_plo);
    size_t base = rid * (SS / 2) + tid * 2;
    bf162 h2, l2;
    split2(a.x * inv, a.y * inv, h2, l2); ph[base] = h2;       pl[base] = l2;
    split2(a.z * inv, a.w * inv, h2, l2); ph[base + 1] = h2;   pl[base + 1] = l2;
    split2(c.x * inv, c.y * inv, h2, l2); ph[base + 512] = h2; pl[base + 512] = l2;
    split2(c.z * inv, c.w * inv, h2, l2); ph[base + 513] = h2; pl[base + 513] = l2;
}

// ---------------- Stage 4: context = probs @ v ----------------
__global__ __launch_bounds__(256, 1) void pv_kernel(float* __restrict__ out) {
    extern __shared__ char sm[];
    const int b = blockIdx.z, bm = blockIdx.y, bn = blockIdx.x;

    float acc[4][4][4];
    ZERO_ACC(acc);
    const size_t ao = ((size_t)b * SS + bm * 128) * SS;
    const size_t bo = ((size_t)b * HH + bn * 128) * SS;
    gemm_core(g_phi + ao, g_plo + ao, SS, g_vthi + bo, g_vtlo + bo, SS,
              SS / KTILE, sm, acc);

    const int lane = threadIdx.x & 31;
    const int warp = threadIdx.x >> 5;
    const int mbase = (warp >> 2) * 64;
    const int nbase = (warp & 3) * 32;
    const int gr = lane >> 2;
    const int gc = (lane & 3) << 1;

#pragma unroll
    for (int im = 0; im < 4; im++) {
#pragma unroll
        for (int in = 0; in < 4; in++) {
            int row = bm * 128 + mbase + im * 16 + gr;
            int col = bn * 128 + nbase + in * 8 + gc;
            size_t o0 = ((size_t)b * SS + row) * HH + col;
            size_t o1 = ((size_t)b * SS + row + 8) * HH + col;
            *reinterpret_cast<float2*>(&out[o0]) = make_float2(acc[im][in][0], acc[im][in][1]);
            *reinterpret_cast<float2*>(&out[o1]) = make_float2(acc[im][in][2], acc[im][in][3]);
        }
    }
}

// ---------------- launch ----------------
extern "C" void kernel_launch(void* const* d_in, const int* in_sizes, int n_in,
                              void* d_out, int out_size) {
    (void)in_sizes; (void)n_in; (void)out_size;
    const float* X  = (const float*)d_in[0];
    const float* am = (const float*)d_in[1];
    const float* pm = (const float*)d_in[2];
    const float* Wq = (const float*)d_in[3];
    const float* bq = (const float*)d_in[4];
    const float* Wk = (const float*)d_in[5];
    const float* bk = (const float*)d_in[6];
    const float* Wv = (const float*)d_in[7];
    const float* bv = (const float*)d_in[8];
    const float* pw = (const float*)d_in[9];
    float* out = (float*)d_out;

    cudaFuncSetAttribute(qkv_kernel,    cudaFuncAttributeMaxDynamicSharedMemorySize, SMEM_DYN);
    cudaFuncSetAttribute(scores_kernel, cudaFuncAttributeMaxDynamicSharedMemorySize, SMEM_DYN);
    cudaFuncSetAttribute(pv_kernel,     cudaFuncAttributeMaxDynamicSharedMemorySize, SMEM_DYN);

    {
        bf162 *xhi2, *xlo2, *whi2, *wlo2;
        cudaGetSymbolAddress((void**)&xhi2, g_xhi);
        cudaGetSymbolAddress((void**)&xlo2, g_xlo);
        cudaGetSymbolAddress((void**)&whi2, g_whi);
        cudaGetSymbolAddress((void**)&wlo2, g_wlo);
        int n4 = (BB * SS * HH) / 4;
        cvt_kernel<<<(n4 + 255) / 256, 256>>>((const float4*)X, xhi2, xlo2, n4);
        int w4 = (HH * HH) / 4;
        cvt_w_kernel<<<dim3((w4 + 255) / 256, 1, 3), 256>>>(
            (const float4*)Wq, (const float4*)Wk, (const float4*)Wv, whi2, wlo2, w4);
    }

    qkv_kernel<<<dim3(HH / 128, (BB * SS) / 128, 3), 256, SMEM_DYN>>>(bq, bk, bv);
    scores_kernel<<<dim3(SS / 128, SS / 128, BB), 256, SMEM_DYN>>>(am, pm, pw);
    softmax_kernel<<<BB * SS, 256>>>();
    pv_kernel<<<dim3(HH / 128, SS / 128, BB), 256, SMEM_DYN>>>(out);
}